// round 5
// baseline (speedup 1.0000x reference)
#include <cuda_runtime.h>

// Problem constants
#define NB 4096
#define NT 512
#define NC 4
#define NH 32
#define NO 3

// Layout: 32-thread blocks (1 warp). Warp handles 2 batch rows,
// 16 lanes per row, each lane owns (h_2g, h_2g+1) in one packed f32x2 reg.
#define ROWS_PER_WARP 2
#define NBLOCKS (NB / ROWS_PER_WARP)   // 2048

__device__ __forceinline__ unsigned long long pk2(float lo, float hi) {
    unsigned long long d;
    asm("mov.b64 %0, {%1, %2};" : "=l"(d) : "f"(lo), "f"(hi));
    return d;
}
__device__ __forceinline__ void upk2(unsigned long long v, float& lo, float& hi) {
    asm("mov.b64 {%0, %1}, %2;" : "=f"(lo), "=f"(hi) : "l"(v));
}
// Packed dual-FMA (FFMA2 in SASS): 2 MACs per issue.
__device__ __forceinline__ unsigned long long fma2(unsigned long long a,
                                                   unsigned long long b,
                                                   unsigned long long c) {
    unsigned long long d;
    asm("fma.rn.f32x2 %0, %1, %2, %3;" : "=l"(d) : "l"(a), "l"(b), "l"(c));
    return d;
}
__device__ __forceinline__ unsigned long long add2(unsigned long long a,
                                                   unsigned long long b) {
    unsigned long long d;
    asm("add.rn.f32x2 %0, %1, %2;" : "=l"(d) : "l"(a), "l"(b));
    return d;
}

__global__ void __launch_bounds__(32)
rnn_fused_kernel(const float* __restrict__ seq,
                 const float* __restrict__ w_ih,
                 const float* __restrict__ w_hh,
                 const float* __restrict__ b_ih,
                 const float* __restrict__ b_hh,
                 const float* __restrict__ fc_w,
                 const float* __restrict__ fc_b,
                 float* __restrict__ out) {
    const int lane = threadIdx.x;        // 0..31
    const int g    = lane & 15;          // lane within row group
    const int half = lane >> 4;          // row within warp (0..1)
    const int row  = blockIdx.x * ROWS_PER_WARP + half;
    const int j0 = 2 * g, j1 = 2 * g + 1;

    // ---- one-time weights into registers, k-packed pairs (k=2p, 2p+1) ----
    unsigned long long wA[NH / 2], wB[NH / 2];
    {
        const float2* wpA = (const float2*)(w_hh + j0 * NH);
        const float2* wpB = (const float2*)(w_hh + j1 * NH);
#pragma unroll
        for (int p = 0; p < NH / 2; p++) {
            const float2 fa = wpA[p];
            const float2 fb = wpB[p];
            wA[p] = pk2(fa.x, fa.y);
            wB[p] = pk2(fb.x, fb.y);
        }
    }
    const unsigned long long wiA0 = pk2(w_ih[j0 * NC + 0], w_ih[j0 * NC + 1]);
    const unsigned long long wiA1 = pk2(w_ih[j0 * NC + 2], w_ih[j0 * NC + 3]);
    const unsigned long long wiB0 = pk2(w_ih[j1 * NC + 0], w_ih[j1 * NC + 1]);
    const unsigned long long wiB1 = pk2(w_ih[j1 * NC + 2], w_ih[j1 * NC + 3]);

    // bias folded as (bias, 0): the end-of-step horizontal add counts it once
    const unsigned long long biasA = pk2(b_ih[j0] + b_hh[j0], 0.0f);
    const unsigned long long biasB = pk2(b_ih[j1] + b_hh[j1], 0.0f);

    // seq for this row: 16 B / timestep; the row's 16 lanes share one address
    // (L1tex broadcast dedup; 2 distinct addresses per warp). 2-step prefetch.
    const float4* sp = (const float4*)(seq + (size_t)row * (NT * NC));
    float4 s0 = sp[0];
    float4 s1 = sp[1];

    // register-resident hidden pair (h_j0, h_j1)
    unsigned long long hpair = 0ULL;

    for (int t = 0; t < NT; t++) {
        const float4 cs = s0;
        s0 = s1;
        const int tn = (t + 2 < NT) ? (t + 2) : (NT - 1);
        s1 = sp[tn];

        const unsigned long long sv = pk2(cs.x, cs.y);
        const unsigned long long sw = pk2(cs.z, cs.w);

        // x_proj seeds (off the h critical chain)
        unsigned long long accA0 = fma2(sv, wiA0, biasA);
        unsigned long long accB0 = fma2(sv, wiB0, biasB);
        unsigned long long accA1 = fma2(sw, wiA1, 0ULL);
        unsigned long long accB1 = fma2(sw, wiB1, 0ULL);

        // recurrence: gather 16 h-pairs via width-16 shuffles;
        // one SHFL serves both rows (both half-warps) at once.
#pragma unroll
        for (int p = 0; p < NH / 2; p++) {
            const unsigned long long hp =
                __shfl_sync(0xffffffffu, hpair, p, 16);
            if (p & 1) {
                accA1 = fma2(wA[p], hp, accA1);
                accB1 = fma2(wB[p], hp, accB1);
            } else {
                accA0 = fma2(wA[p], hp, accA0);
                accB0 = fma2(wB[p], hp, accB0);
            }
        }

        // horizontal reduce + relu + repack (registers only)
        float aLo, aHi, bLo, bHi;
        upk2(add2(accA0, accA1), aLo, aHi);
        upk2(add2(accB0, accB1), bLo, bHi);
        const float a = fmaxf(aLo + aHi, 0.0f);
        const float b = fmaxf(bLo + bHi, 0.0f);
        hpair = pk2(a, b);
    }

    // ---- FC head: per-lane partials, width-16 xor reduction ----
    float hLo, hHi;
    upk2(hpair, hLo, hHi);
    float po[NO];
#pragma unroll
    for (int o = 0; o < NO; o++)
        po[o] = fmaf(hLo, fc_w[o * NH + j0], hHi * fc_w[o * NH + j1]);
#pragma unroll
    for (int off = 8; off >= 1; off >>= 1) {
#pragma unroll
        for (int o = 0; o < NO; o++)
            po[o] += __shfl_xor_sync(0xffffffffu, po[o], off, 16);
    }
    if (g == 0) {
#pragma unroll
        for (int o = 0; o < NO; o++)
            out[row * NO + o] = po[o] + fc_b[o];
    }
}

extern "C" void kernel_launch(void* const* d_in, const int* in_sizes, int n_in,
                              void* d_out, int out_size) {
    const float* seq  = (const float*)d_in[0];
    const float* w_ih = (const float*)d_in[1];
    const float* w_hh = (const float*)d_in[2];
    const float* b_ih = (const float*)d_in[3];
    const float* b_hh = (const float*)d_in[4];
    const float* fc_w = (const float*)d_in[5];
    const float* fc_b = (const float*)d_in[6];
    float* out = (float*)d_out;

    rnn_fused_kernel<<<NBLOCKS, 32>>>(seq, w_ih, w_hh, b_ih, b_hh,
                                      fc_w, fc_b, out);
}

// round 6
// speedup vs baseline: 1.4437x; 1.4437x over previous
#include <cuda_runtime.h>

// Problem constants
#define NB 4096
#define NT 512
#define NC 4
#define NH 32
#define NO 3

// Layout: 32-thread blocks (1 warp). Warp handles 4 batch rows,
// 8 lanes per row, each lane owns h[4q..4q+3] (j-ownership) and the
// matching 4 rows of w_hh in registers.
#define ROWS_PER_WARP 4
#define NBLOCKS (NB / ROWS_PER_WARP)   // 1024

// smem h tile: double-buffered, 4 rows x 40 floats (32 h + 8 pad so row r
// starts at bank 8r -> the 4 distinct addresses of each broadcast LDS are
// conflict-free).
#define HROW 40
#define HBUF (ROWS_PER_WARP * HROW)    // 160 floats per buffer

__device__ __forceinline__ unsigned long long pk2(float lo, float hi) {
    unsigned long long d;
    asm("mov.b64 %0, {%1, %2};" : "=l"(d) : "f"(lo), "f"(hi));
    return d;
}
__device__ __forceinline__ void upk2(unsigned long long v, float& lo, float& hi) {
    asm("mov.b64 {%0, %1}, %2;" : "=f"(lo), "=f"(hi) : "l"(v));
}
// Packed dual-FMA (FFMA2 in SASS): 2 MACs per issue.
__device__ __forceinline__ unsigned long long fma2(unsigned long long a,
                                                   unsigned long long b,
                                                   unsigned long long c) {
    unsigned long long d;
    asm("fma.rn.f32x2 %0, %1, %2, %3;" : "=l"(d) : "l"(a), "l"(b), "l"(c));
    return d;
}
__device__ __forceinline__ unsigned long long add2(unsigned long long a,
                                                   unsigned long long b) {
    unsigned long long d;
    asm("add.rn.f32x2 %0, %1, %2;" : "=l"(d) : "l"(a), "l"(b));
    return d;
}
__device__ __forceinline__ void lds_2x64(unsigned addr, unsigned long long& a,
                                         unsigned long long& b) {
    asm volatile("ld.shared.v2.u64 {%0, %1}, [%2];" : "=l"(a), "=l"(b) : "r"(addr));
}
__device__ __forceinline__ void sts_v4(unsigned addr, float a, float b, float c, float d) {
    asm volatile("st.shared.v4.b32 [%0], {%1, %2, %3, %4};"
                 :: "r"(addr), "f"(a), "f"(b), "f"(c), "f"(d) : "memory");
}

__global__ void __launch_bounds__(32)
rnn_fused_kernel(const float* __restrict__ seq,
                 const float* __restrict__ w_ih,
                 const float* __restrict__ w_hh,
                 const float* __restrict__ b_ih,
                 const float* __restrict__ b_hh,
                 const float* __restrict__ fc_w,
                 const float* __restrict__ fc_b,
                 float* __restrict__ out) {
    __shared__ float hs[2 * HBUF];

    const int lane = threadIdx.x;        // 0..31
    const int q    = lane & 7;           // lane within row group
    const int r    = lane >> 3;          // row within warp (0..3)
    const int row  = blockIdx.x * ROWS_PER_WARP + r;
    const int jb   = 4 * q;              // first owned hidden index

    // ---- one-time weights into registers ----
    unsigned long long w2[4][NH / 2];
#pragma unroll
    for (int jj = 0; jj < 4; jj++) {
        const float2* wp = (const float2*)(w_hh + (jb + jj) * NH);
#pragma unroll
        for (int p = 0; p < NH / 2; p++) {
            const float2 f = wp[p];
            w2[jj][p] = pk2(f.x, f.y);
        }
    }
    unsigned long long wiE[4], wiO[4], bias[4];
#pragma unroll
    for (int jj = 0; jj < 4; jj++) {
        const int j = jb + jj;
        wiE[jj]  = pk2(w_ih[j * NC + 0], w_ih[j * NC + 1]);
        wiO[jj]  = pk2(w_ih[j * NC + 2], w_ih[j * NC + 3]);
        bias[jj] = pk2(b_ih[j] + b_hh[j], 0.0f);   // counted once by horizontal add
    }

    // smem addresses
    const unsigned hbase = (unsigned)__cvta_generic_to_shared(hs);
    const unsigned myrow = hbase + r * (HROW * 4);            // buffer 0, own row
    const unsigned mywr  = myrow + q * 16;                    // own 16B write slot

    // seq for this row: 16 B / step, broadcast across the row's 8 lanes
    // (4 distinct addresses per warp, L1tex dedup). 2-step register prefetch.
    const float4* sp = (const float4*)(seq + (size_t)row * (NT * NC));
    float4 s0 = sp[0];
    float4 s1 = sp[1];

    // h(t=0) = 0 in buffer 0
    sts_v4(mywr, 0.f, 0.f, 0.f, 0.f);
    __syncwarp();

    float v0, v1, v2, v3;   // lane's 4 current h values (live after each step)

    for (int t = 0; t < NT; t++) {
        const int par = t & 1;
        const unsigned rdrow = myrow + par * (HBUF * 4);        // read buf[par]
        const unsigned wrslot = mywr + (par ^ 1) * (HBUF * 4);  // write buf[par^1]

        const float4 cs = s0;
        s0 = s1;
        const int tn = (t + 2 < NT) ? (t + 2) : (NT - 1);
        s1 = sp[tn];

        const unsigned long long sv = pk2(cs.x, cs.y);
        const unsigned long long sw = pk2(cs.z, cs.w);

        // x_proj seeds (independent of h gather)
        unsigned long long aE0 = fma2(sv, wiE[0], bias[0]);
        unsigned long long aE1 = fma2(sv, wiE[1], bias[1]);
        unsigned long long aE2 = fma2(sv, wiE[2], bias[2]);
        unsigned long long aE3 = fma2(sv, wiE[3], bias[3]);
        unsigned long long aO0 = fma2(sw, wiO[0], 0ULL);
        unsigned long long aO1 = fma2(sw, wiO[1], 0ULL);
        unsigned long long aO2 = fma2(sw, wiO[2], 0ULL);
        unsigned long long aO3 = fma2(sw, wiO[3], 0ULL);

        // gather all 32 h of own row: 8 broadcast LDS (4 distinct addrs each,
        // conflict-free by row padding), pairs p=2i (->E chains), 2i+1 (->O).
#pragma unroll
        for (int i = 0; i < NH / 4; i++) {
            unsigned long long h0, h1;
            lds_2x64(rdrow + i * 16, h0, h1);
            aE0 = fma2(w2[0][2 * i], h0, aE0);
            aE1 = fma2(w2[1][2 * i], h0, aE1);
            aE2 = fma2(w2[2][2 * i], h0, aE2);
            aE3 = fma2(w2[3][2 * i], h0, aE3);
            aO0 = fma2(w2[0][2 * i + 1], h1, aO0);
            aO1 = fma2(w2[1][2 * i + 1], h1, aO1);
            aO2 = fma2(w2[2][2 * i + 1], h1, aO2);
            aO3 = fma2(w2[3][2 * i + 1], h1, aO3);
        }

        // horizontal reduce + relu
        float lo0, hi0, lo1, hi1, lo2, hi2, lo3, hi3;
        upk2(add2(aE0, aO0), lo0, hi0);
        upk2(add2(aE1, aO1), lo1, hi1);
        upk2(add2(aE2, aO2), lo2, hi2);
        upk2(add2(aE3, aO3), lo3, hi3);
        v0 = fmaxf(lo0 + hi0, 0.0f);
        v1 = fmaxf(lo1 + hi1, 0.0f);
        v2 = fmaxf(lo2 + hi2, 0.0f);
        v3 = fmaxf(lo3 + hi3, 0.0f);

        // publish own 4 h for next step
        sts_v4(wrslot, v0, v1, v2, v3);
        __syncwarp();
    }

    // ---- FC head: partials over owned 4 h, width-8 xor reduction ----
    float po[NO];
#pragma unroll
    for (int o = 0; o < NO; o++) {
        const float* fw = fc_w + o * NH + jb;
        po[o] = fmaf(v0, fw[0],
                fmaf(v1, fw[1],
                fmaf(v2, fw[2], v3 * fw[3])));
    }
#pragma unroll
    for (int off = 4; off >= 1; off >>= 1) {
#pragma unroll
        for (int o = 0; o < NO; o++)
            po[o] += __shfl_xor_sync(0xffffffffu, po[o], off, 8);
    }
    if (q == 0) {
#pragma unroll
        for (int o = 0; o < NO; o++)
            out[row * NO + o] = po[o] + fc_b[o];
    }
}

extern "C" void kernel_launch(void* const* d_in, const int* in_sizes, int n_in,
                              void* d_out, int out_size) {
    const float* seq  = (const float*)d_in[0];
    const float* w_ih = (const float*)d_in[1];
    const float* w_hh = (const float*)d_in[2];
    const float* b_ih = (const float*)d_in[3];
    const float* b_hh = (const float*)d_in[4];
    const float* fc_w = (const float*)d_in[5];
    const float* fc_b = (const float*)d_in[6];
    float* out = (float*)d_out;

    rnn_fused_kernel<<<NBLOCKS, 32>>>(seq, w_ih, w_hh, b_ih, b_hh,
                                      fc_w, fc_b, out);
}